// round 3
// baseline (speedup 1.0000x reference)
#include <cuda_runtime.h>
#include <cstdint>

#define NN 50000
#define HH 64
#define NEE 250000

typedef unsigned long long ull;

// ---------------- scratch (device globals; no runtime allocation) ----------------
// Only edge types {0,1,3,5,7} are ever used -> index by t, max 7 -> size 8.
__device__ __align__(16) float g_Q[8][NN * HH];
__device__ __align__(16) float g_K[8][NN * HH];
__device__ __align__(16) float g_V[8][NN * HH];
__device__ __align__(16) float g_O1[NN * HH];    // layer-1 output, node type 1
__device__ __align__(16) float g_O2[NN * HH];    // layer-1 output, node type 2
__device__ __align__(16) float g_OUT2[NN * HH];  // layer-2 output, node type 2
__device__ __align__(16) unsigned g_m[8][NN];    // per-pass softmax max (ordered-uint)
__device__ __align__(16) float g_den[8][NN];     // per-pass softmax denom
__device__ __align__(16) float g_alpha[8][NEE];  // per-pass raw attention logits

// ---------------- tables ----------------
__constant__ int c_src[9] = {0, 0, 0, 1, 1, 1, 2, 2, 3};
__constant__ int c_dst[9] = {1, 2, 3, 2, 3, 1, 3, 2, 3};
__constant__ int c_l1t[5] = {0, 1, 3, 5, 7};  // layer-1 live edge types
__constant__ int c_l2t[3] = {1, 3, 7};        // layer-2 live edge types
__constant__ int c_p2t[8] = {0, 1, 3, 5, 7, 1, 3, 7};  // pass -> edge type
__constant__ int c_p2l[8] = {0, 0, 0, 0, 0, 1, 1, 1};  // pass -> layer
__constant__ int c_p2o[8] = {0, 1, 1, 0, 1, 2, 2, 2};  // pass -> out buf (0=O1,1=O2,2=OUT2)

// ---------------- helpers ----------------
__device__ __forceinline__ ull pack2(float x, float y) {
    ull r; asm("mov.b64 %0, {%1, %2};" : "=l"(r) : "f"(x), "f"(y)); return r;
}
__device__ __forceinline__ void unpack2(ull v, float& x, float& y) {
    asm("mov.b64 {%0, %1}, %2;" : "=f"(x), "=f"(y) : "l"(v));
}
__device__ __forceinline__ void fma2(ull& a, ull x, ull w) {
    asm("fma.rn.f32x2 %0, %1, %2, %0;" : "+l"(a) : "l"(x), "l"(w));
}
__device__ __forceinline__ void redv4(float* p, float x, float y, float z, float w) {
    asm volatile("red.global.add.v4.f32 [%0], {%1,%2,%3,%4};"
                 :: "l"(p), "f"(x), "f"(y), "f"(z), "f"(w) : "memory");
}
// order-preserving float<->uint map (monotone; 0 is below every real value)
__device__ __forceinline__ unsigned ordf(float f) {
    unsigned u = __float_as_uint(f);
    return (u & 0x80000000u) ? ~u : (u | 0x80000000u);
}
__device__ __forceinline__ float deord(unsigned u) {
    return (u & 0x80000000u) ? __uint_as_float(u & 0x7fffffffu) : __uint_as_float(~u);
}

// ---------------- init: zero all accumulators (runs every replay) ----------------
__global__ void init_kernel() {
    int i = (blockIdx.x * 256 + threadIdx.x) * 4;
    float4 z = make_float4(0.f, 0.f, 0.f, 0.f);
    if (i < NN * HH) {
        *(float4*)(g_O1 + i) = z;
        *(float4*)(g_O2 + i) = z;
        *(float4*)(g_OUT2 + i) = z;
    }
    if (i < 8 * NN) {
        *(uint4*)(&g_m[0][0] + i) = make_uint4(0u, 0u, 0u, 0u);
        *(float4*)(&g_den[0][0] + i) = z;
    }
}

// ---------------- fused GEMM: all Q/K/V/skip projections of one layer ----------------
// grid: (ceil(N/128), njobs). job = 4*type_slot + role; role 0=Q,1=K,2=V,3=skip.
// 2 rows x 16 cols per thread, f32x2 FMA. smem = 16KB W + 32KB X^T = 48KB exactly.
__global__ void __launch_bounds__(256, 3) gemm_kernel(
    const float* __restrict__ x0, const float* __restrict__ x1,
    const float* __restrict__ x2, const float* __restrict__ x3,
    const float* __restrict__ Wq, const float* __restrict__ bq,
    const float* __restrict__ Wk, const float* __restrict__ bk,
    const float* __restrict__ Wv, const float* __restrict__ bv,
    const float* __restrict__ Ws, const float* __restrict__ bs,
    int layer)
{
    __shared__ __align__(16) float sW[64 * 64];
    __shared__ __align__(16) float sX[64 * 128];  // transposed: sX[k*128 + r]

    if (layer) { x1 = g_O1; x2 = g_O2; }  // layer-2 inputs are relu'd layer-1 outputs

    int job = blockIdx.y;
    int t = (layer == 0) ? c_l1t[job >> 2] : c_l2t[job >> 2];
    int role = job & 3;
    int s = c_src[t], d = c_dst[t];
    int insel = (role == 1 || role == 2) ? s : d;
    const float* X = (insel == 0) ? x0 : (insel == 1) ? x1 : (insel == 2) ? x2 : x3;
    int wo = layer * 9 + t;
    const float* W; const float* B;
    if (role == 0)      { W = Wq + wo * 4096; B = bq + wo * 64; }
    else if (role == 1) { W = Wk + wo * 4096; B = bk + wo * 64; }
    else if (role == 2) { W = Wv + wo * 4096; B = bv + wo * 64; }
    else                { W = Ws + wo * 4096; B = bs + wo * 64; }
    float* OUT;
    if (role == 0)      OUT = g_Q[t];
    else if (role == 1) OUT = g_K[t];
    else if (role == 2) OUT = g_V[t];
    else                OUT = layer ? g_OUT2 : (d == 1 ? g_O1 : g_O2);

    int tid = threadIdx.x;
    int row0 = blockIdx.x * 128;

    // stage W [64][64]
    for (int i = tid * 4; i < 4096; i += 1024)
        *(float4*)(sW + i) = *(const float4*)(W + i);
    // stage X tile transposed
    for (int i = tid; i < 128 * 16; i += 256) {
        int rl = i >> 4, kq = (i & 15) * 4;
        int r = row0 + rl;
        float4 v = make_float4(0.f, 0.f, 0.f, 0.f);
        if (r < NN) v = *(const float4*)(X + r * 64 + kq);
        sX[(kq + 0) * 128 + rl] = v.x;
        sX[(kq + 1) * 128 + rl] = v.y;
        sX[(kq + 2) * 128 + rl] = v.z;
        sX[(kq + 3) * 128 + rl] = v.w;
    }
    __syncthreads();

    int cg = tid & 3;   // column group: cols [cg*16, cg*16+16)
    int rg = tid >> 2;  // row group: rows rg*2, rg*2+1
    int c0 = cg * 16;

    ull acc0[8], acc1[8];
    const ull* B64 = (const ull*)(B + c0);
    #pragma unroll
    for (int j = 0; j < 8; j++) { acc0[j] = B64[j]; acc1[j] = acc0[j]; }

    #pragma unroll 8
    for (int k = 0; k < 64; k++) {
        float2 xv = *(const float2*)(sX + k * 128 + (rg << 1));
        ull xa = pack2(xv.x, xv.x);
        ull xb = pack2(xv.y, xv.y);
        const longlong2* wr = (const longlong2*)(sW + k * 64 + c0);
        #pragma unroll
        for (int q = 0; q < 4; q++) {
            longlong2 w = wr[q];
            fma2(acc0[2 * q + 0], xa, (ull)w.x);
            fma2(acc0[2 * q + 1], xa, (ull)w.y);
            fma2(acc1[2 * q + 0], xb, (ull)w.x);
            fma2(acc1[2 * q + 1], xb, (ull)w.y);
        }
    }

    int r0 = row0 + (rg << 1);
    if (role != 3) {
        if (r0 < NN) {
            ull* o = (ull*)(OUT + r0 * 64 + c0);
            #pragma unroll
            for (int j = 0; j < 8; j++) o[j] = acc0[j];
        }
        if (r0 + 1 < NN) {
            ull* o = (ull*)(OUT + (r0 + 1) * 64 + c0);
            #pragma unroll
            for (int j = 0; j < 8; j++) o[j] = acc1[j];
        }
    } else {
        if (r0 < NN) {
            float* o = OUT + r0 * 64 + c0;
            #pragma unroll
            for (int q = 0; q < 4; q++) {
                float a, b, c, dd;
                unpack2(acc0[2 * q], a, b); unpack2(acc0[2 * q + 1], c, dd);
                redv4(o + q * 4, a, b, c, dd);
            }
        }
        if (r0 + 1 < NN) {
            float* o = OUT + (r0 + 1) * 64 + c0;
            #pragma unroll
            for (int q = 0; q < 4; q++) {
                float a, b, c, dd;
                unpack2(acc1[2 * q], a, b); unpack2(acc1[2 * q + 1], c, dd);
                redv4(o + q * 4, a, b, c, dd);
            }
        }
    }
}

// ---------------- pass A: logits + segment max. 8 lanes per edge. ----------------
__global__ void __launch_bounds__(256) passA_kernel(
    const int* __restrict__ EI, const float* __restrict__ EA,
    const float* __restrict__ We, int pbase)
{
    int p = pbase + blockIdx.y;
    int t = c_p2t[p];
    __shared__ __align__(16) float sWe[128];
    if (threadIdx.x < 32)
        ((float4*)sWe)[threadIdx.x] = ((const float4*)(We + (c_p2l[p] * 9 + t) * 128))[threadIdx.x];
    __syncthreads();

    int lane = threadIdx.x & 7;
    int eid = blockIdx.x * 32 + (threadIdx.x >> 3);
    if (eid >= NEE) return;
    int src = EI[t * 2 * NEE + eid];
    int dst = EI[t * 2 * NEE + NEE + eid];
    float2 ea = *(const float2*)(EA + (size_t)t * NEE * 2 + eid * 2);

    const float4* Q4 = (const float4*)(g_Q[t] + dst * 64 + lane * 8);
    const float4* K4 = (const float4*)(g_K[t] + src * 64 + lane * 8);
    const float4* W0 = (const float4*)(sWe) + lane * 2;
    const float4* W1 = (const float4*)(sWe + 64) + lane * 2;

    float part = 0.f;
    #pragma unroll
    for (int c = 0; c < 2; c++) {
        float4 q = Q4[c], kk = K4[c], w0 = W0[c], w1 = W1[c];
        float kx = fmaf(ea.x, w0.x, fmaf(ea.y, w1.x, kk.x));
        float ky = fmaf(ea.x, w0.y, fmaf(ea.y, w1.y, kk.y));
        float kz = fmaf(ea.x, w0.z, fmaf(ea.y, w1.z, kk.z));
        float kw = fmaf(ea.x, w0.w, fmaf(ea.y, w1.w, kk.w));
        part = fmaf(q.x, kx, part);
        part = fmaf(q.y, ky, part);
        part = fmaf(q.z, kz, part);
        part = fmaf(q.w, kw, part);
    }
    part += __shfl_xor_sync(0xffffffffu, part, 1);
    part += __shfl_xor_sync(0xffffffffu, part, 2);
    part += __shfl_xor_sync(0xffffffffu, part, 4);
    if (lane == 0) {
        float alpha = part * 0.125f;  // 1/sqrt(64)
        g_alpha[p][eid] = alpha;
        atomicMax(&g_m[p][dst], ordf(alpha));
    }
}

// ---------------- pass B: segment sum of exp ----------------
__global__ void __launch_bounds__(256) passB_kernel(const int* __restrict__ EI, int pbase) {
    int p = pbase + blockIdx.y;
    int t = c_p2t[p];
    int eid = blockIdx.x * 256 + threadIdx.x;
    if (eid >= NEE) return;
    int dst = EI[t * 2 * NEE + NEE + eid];
    float a = g_alpha[p][eid];
    float m = deord(g_m[p][dst]);
    atomicAdd(&g_den[p][dst], __expf(a - m));
}

// ---------------- pass C: weighted aggregate into layer output ----------------
__global__ void __launch_bounds__(256) passC_kernel(
    const int* __restrict__ EI, const float* __restrict__ EA,
    const float* __restrict__ We, int pbase)
{
    int p = pbase + blockIdx.y;
    int t = c_p2t[p];
    __shared__ __align__(16) float sWe[128];
    if (threadIdx.x < 32)
        ((float4*)sWe)[threadIdx.x] = ((const float4*)(We + (c_p2l[p] * 9 + t) * 128))[threadIdx.x];
    __syncthreads();

    int lane = threadIdx.x & 7;
    int eid = blockIdx.x * 32 + (threadIdx.x >> 3);
    if (eid >= NEE) return;
    int src = EI[t * 2 * NEE + eid];
    int dst = EI[t * 2 * NEE + NEE + eid];
    float2 ea = *(const float2*)(EA + (size_t)t * NEE * 2 + eid * 2);

    float a = g_alpha[p][eid];
    float m = deord(g_m[p][dst]);
    float den = g_den[p][dst];
    float wgt = __expf(a - m) / (den + 1e-16f);

    int os = c_p2o[p];
    float* O = (os == 0) ? g_O1 : (os == 1) ? g_O2 : g_OUT2;
    const float4* V4 = (const float4*)(g_V[t] + src * 64 + lane * 8);
    const float4* W0 = (const float4*)(sWe) + lane * 2;
    const float4* W1 = (const float4*)(sWe + 64) + lane * 2;
    float* Or = O + dst * 64 + lane * 8;

    #pragma unroll
    for (int c = 0; c < 2; c++) {
        float4 v = V4[c], w0 = W0[c], w1 = W1[c];
        float vx = fmaf(ea.x, w0.x, fmaf(ea.y, w1.x, v.x)) * wgt;
        float vy = fmaf(ea.x, w0.y, fmaf(ea.y, w1.y, v.y)) * wgt;
        float vz = fmaf(ea.x, w0.z, fmaf(ea.y, w1.z, v.z)) * wgt;
        float vw = fmaf(ea.x, w0.w, fmaf(ea.y, w1.w, v.w)) * wgt;
        redv4(Or + c * 4, vx, vy, vz, vw);
    }
}

// ---------------- relu on layer-1 outputs ----------------
__global__ void relu_kernel() {
    int i = (blockIdx.x * 256 + threadIdx.x) * 4;
    if (i < NN * HH) {
        float4 a = *(float4*)(g_O1 + i);
        a.x = fmaxf(a.x, 0.f); a.y = fmaxf(a.y, 0.f);
        a.z = fmaxf(a.z, 0.f); a.w = fmaxf(a.w, 0.f);
        *(float4*)(g_O1 + i) = a;
        float4 b = *(float4*)(g_O2 + i);
        b.x = fmaxf(b.x, 0.f); b.y = fmaxf(b.y, 0.f);
        b.z = fmaxf(b.z, 0.f); b.w = fmaxf(b.w, 0.f);
        *(float4*)(g_O2 + i) = b;
    }
}

// ---------------- final: relu(OUT2) @ lin_W + lin_b. 8 lanes per row. ----------------
__global__ void __launch_bounds__(256) final_kernel(
    const float* __restrict__ linW, const float* __restrict__ linb, float* __restrict__ out)
{
    __shared__ __align__(16) float4 sLW[64];
    if (threadIdx.x < 64) sLW[threadIdx.x] = *(const float4*)(linW + threadIdx.x * 4);
    __syncthreads();
    int lane = threadIdx.x & 7;
    int row = blockIdx.x * 32 + (threadIdx.x >> 3);
    if (row >= NN) return;
    const float* X = g_OUT2 + row * 64 + lane * 8;
    float4 acc = make_float4(0.f, 0.f, 0.f, 0.f);
    #pragma unroll
    for (int c = 0; c < 8; c++) {
        float x = fmaxf(X[c], 0.f);
        float4 wv = sLW[lane * 8 + c];
        acc.x = fmaf(x, wv.x, acc.x);
        acc.y = fmaf(x, wv.y, acc.y);
        acc.z = fmaf(x, wv.z, acc.z);
        acc.w = fmaf(x, wv.w, acc.w);
    }
    #pragma unroll
    for (int off = 1; off < 8; off <<= 1) {
        acc.x += __shfl_xor_sync(0xffffffffu, acc.x, off);
        acc.y += __shfl_xor_sync(0xffffffffu, acc.y, off);
        acc.z += __shfl_xor_sync(0xffffffffu, acc.z, off);
        acc.w += __shfl_xor_sync(0xffffffffu, acc.w, off);
    }
    if (lane == 0) {
        float4 b = *(const float4*)linb;
        acc.x += b.x; acc.y += b.y; acc.z += b.z; acc.w += b.w;
        *(float4*)(out + row * 4) = acc;
    }
}

// ---------------- launcher ----------------
extern "C" void kernel_launch(void* const* d_in, const int* in_sizes, int n_in,
                              void* d_out, int out_size) {
    (void)in_sizes; (void)n_in; (void)out_size;
    const float* x0 = (const float*)d_in[0];
    const float* x1 = (const float*)d_in[1];
    const float* x2 = (const float*)d_in[2];
    const float* x3 = (const float*)d_in[3];
    const int*   EI = (const int*)d_in[4];
    const float* EA = (const float*)d_in[5];
    const float* Wq = (const float*)d_in[6];
    const float* bq = (const float*)d_in[7];
    const float* Wk = (const float*)d_in[8];
    const float* bk = (const float*)d_in[9];
    const float* Wv = (const float*)d_in[10];
    const float* bv = (const float*)d_in[11];
    const float* We = (const float*)d_in[12];
    const float* Ws = (const float*)d_in[13];
    const float* bs = (const float*)d_in[14];
    const float* lW = (const float*)d_in[15];
    const float* lb = (const float*)d_in[16];
    float* out = (float*)d_out;

    const int ROWB = (NN + 127) / 128;       // 391
    const int EB32 = (NEE + 31) / 32;        // 7813
    const int EB256 = (NEE + 255) / 256;     // 977

    init_kernel<<<3125, 256>>>();

    // ---- layer 1: 5 live edge types ----
    gemm_kernel<<<dim3(ROWB, 20), 256>>>(x0, x1, x2, x3, Wq, bq, Wk, bk, Wv, bv, Ws, bs, 0);
    passA_kernel<<<dim3(EB32, 5), 256>>>(EI, EA, We, 0);
    passB_kernel<<<dim3(EB256, 5), 256>>>(EI, 0);
    passC_kernel<<<dim3(EB32, 5), 256>>>(EI, EA, We, 0);
    relu_kernel<<<3125, 256>>>();

    // ---- layer 2: 3 live edge types (d==2 only) ----
    gemm_kernel<<<dim3(ROWB, 12), 256>>>(x0, x1, x2, x3, Wq, bq, Wk, bk, Wv, bv, Ws, bs, 1);
    passA_kernel<<<dim3(EB32, 3), 256>>>(EI, EA, We, 5);
    passB_kernel<<<dim3(EB256, 3), 256>>>(EI, 5);
    passC_kernel<<<dim3(EB32, 3), 256>>>(EI, EA, We, 5);

    final_kernel<<<(NN + 31) / 32, 256>>>(lW, lb, out);
}